// round 15
// baseline (speedup 1.0000x reference)
#include <cuda_runtime.h>
#include <math.h>

// FraudDetectionHybrid — autoencoder branch is dead code (recon unused).
// R15: R13's 2-D table (fold layers 2-4 + conv + sampler + softmax into
// G2(h0,h1), measured rel_err 1.64e-4 at delta=1/48) with its three failure
// modes fixed: (1) MLP=4 upfront input loads (R13's grid-stride MLP=1 loop
// was the real 11.7us cause), (2) staging traffic cut 4x via grid=296
// (2 blocks/SM, 11MB total), (3) exact-cover guarded launch. Per sample:
// 2 MUFU + 4 LDS + ~14 FMA instead of 14 MUFU + ~30 FMA.

#define TN    97
#define TPAD  9412                      // 97*97=9409 padded to /4
#define GRID  296
#define BLOCK 512
#define STRIDE (GRID * BLOCK)           // 151552 threads

__device__ float g_tab2[TPAD];

__device__ __forceinline__ float tanh_fast(float x) {
    float y;
    asm("tanh.approx.f32 %0, %1;" : "=f"(y) : "f"(x));
    return y;
}

// ---------------- kernel 1: build G2 table (accurate math, tiny) ----------------
__global__ __launch_bounds__(256)
void build_table(const float4* __restrict__ fraud_W,   // [4,2,2] = 4 float4
                 const float4* __restrict__ fraud_b,   // [4,2]   = 2 float4
                 const float4* __restrict__ conv_k,
                 const float4* __restrict__ s_W1,
                 const float4* __restrict__ s_b1,
                 const float4* __restrict__ s_W2,
                 const float2* __restrict__ s_b2)
{
    const int idx = blockIdx.x * blockDim.x + threadIdx.x;
    if (idx >= TN * TN) return;
    const int ix = idx % TN;            // h0 axis
    const int iy = idx / TN;            // h1 axis
    float h0 = (float)ix * (1.0f / 48.0f) - 1.0f;
    float h1 = (float)iy * (1.0f / 48.0f) - 1.0f;

    const float4 w1  = __ldg(fraud_W + 1);
    const float4 w2  = __ldg(fraud_W + 2);
    const float4 w3  = __ldg(fraud_W + 3);
    const float4 fb0 = __ldg(fraud_b + 0);
    const float4 fb1 = __ldg(fraud_b + 1);
    const float4 ck  = __ldg(conv_k);
    const float4 W1a = __ldg(s_W1 + 0);
    const float4 W1b = __ldg(s_W1 + 1);
    const float4 b1  = __ldg(s_b1);
    const float4 W2a = __ldg(s_W2 + 0);
    const float4 W2b = __ldg(s_W2 + 1);
    const float2 b2  = __ldg(s_b2);

    // fraud layers 2..4 (accurate tanh)
    float z0 = fmaf(w1.x, h0, fmaf(w1.y, h1, fb0.z));
    float z1 = fmaf(w1.z, h0, fmaf(w1.w, h1, fb0.w));
    h0 = tanhf(z0); h1 = tanhf(z1);
    z0 = fmaf(w2.x, h0, fmaf(w2.y, h1, fb1.x));
    z1 = fmaf(w2.z, h0, fmaf(w2.w, h1, fb1.y));
    h0 = tanhf(z0); h1 = tanhf(z1);
    z0 = fmaf(w3.x, h0, fmaf(w3.y, h1, fb1.z));
    z1 = fmaf(w3.z, h0, fmaf(w3.w, h1, fb1.w));
    h0 = tanhf(z0); h1 = tanhf(z1);
    // collapsed conv + sigmoid
    float zc   = fmaf(ck.x + ck.z, h0, (ck.y + ck.w) * h1);
    float conv = 1.0f / (1.0f + expf(-zc));
    // sampler 2->4 tanh
    float t0 = tanhf(fmaf(W1a.x, h0, fmaf(W1a.y, conv, b1.x)));
    float t1 = tanhf(fmaf(W1a.z, h0, fmaf(W1a.w, conv, b1.y)));
    float t2 = tanhf(fmaf(W1b.x, h0, fmaf(W1b.y, conv, b1.z)));
    float t3 = tanhf(fmaf(W1b.z, h0, fmaf(W1b.w, conv, b1.w)));
    // dl = l1 - l0 ; p0 = 1/(1+exp(dl))
    float dl = fmaf(t3, W2b.w - W2a.w, fmaf(t2, W2b.z - W2a.z,
               fmaf(t1, W2b.y - W2a.y, fmaf(t0, W2b.x - W2a.x, b2.y - b2.x))));
    g_tab2[idx] = 1.0f / (1.0f + expf(dl));
}

// ---------------- kernel 2: layer-1 tanh + smem bilinear ----------------
__global__ __launch_bounds__(BLOCK, 2)
void fraud_kernel(const float4* __restrict__ x4,
                  const float4* __restrict__ fraud_W,   // row 0 only
                  const float4* __restrict__ fraud_b,   // first 2 floats only
                  float4* __restrict__ out4,
                  int n4)
{
    extern __shared__ float tab[];      // TPAD floats (37.6 KB)

    const int base = blockIdx.x * BLOCK + threadIdx.x;
    const bool has3 = (base + 3 * STRIDE) < n4;

    // ---- ALL input loads in flight FIRST (MLP=4; R13's fatal bug fixed) ----
    float4 in0 = x4[base];
    float4 in1 = x4[base + STRIDE];
    float4 in2 = x4[base + 2 * STRIDE];
    float4 in3 = has3 ? x4[base + 3 * STRIDE] : make_float4(0.f, 0.f, 0.f, 0.f);

    // ---- cooperative table stage: 2353 float4 over 512 threads ----
    {
        const float4* src = reinterpret_cast<const float4*>(g_tab2);
        float4* dst = reinterpret_cast<float4*>(tab);
#pragma unroll
        for (int k = 0; k < 5; k++) {
            int i = threadIdx.x + k * BLOCK;
            if (i < TPAD / 4) dst[i] = src[i];
        }
    }

    const float4 w0  = __ldg(fraud_W);        // layer-1 weights
    const float4 fb0 = __ldg(fraud_b);        // .x,.y = layer-1 biases
    __syncthreads();

    auto process = [&](float x0, float x1, float& p0, float& p1) {
        // fraud layer 1 (only MUFU work left)
        float h0 = tanh_fast(fmaf(w0.x, x0, fmaf(w0.y, x1, fb0.x)));
        float h1 = tanh_fast(fmaf(w0.z, x0, fmaf(w0.w, x1, fb0.y)));
        // bilinear lookup of G2(h0,h1); tanh.approx output in [-1,1] -> u,v in [0,96]
        float u = fmaf(h0, 48.0f, 48.0f);
        float v = fmaf(h1, 48.0f, 48.0f);
        int ix = min(__float2int_rd(u), TN - 2);
        int iy = min(__float2int_rd(v), TN - 2);
        float fx = u - (float)ix;
        float fy = v - (float)iy;
        const float* r = tab + iy * TN + ix;
        float v00 = r[0];
        float v01 = r[1];
        float v10 = r[TN];
        float v11 = r[TN + 1];
        float g0 = fmaf(fx, v01 - v00, v00);
        float g1 = fmaf(fx, v11 - v10, v10);
        p0 = fmaf(fy, g1 - g0, g0);
        p1 = 1.0f - p0;
    };

    float4 r0, r1, r2, r3;
    process(in0.x, in0.y, r0.x, r0.y);
    process(in0.z, in0.w, r0.z, r0.w);
    process(in1.x, in1.y, r1.x, r1.y);
    process(in1.z, in1.w, r1.z, r1.w);
    process(in2.x, in2.y, r2.x, r2.y);
    process(in2.z, in2.w, r2.z, r2.w);
    process(in3.x, in3.y, r3.x, r3.y);
    process(in3.z, in3.w, r3.z, r3.w);

    out4[base]              = r0;
    out4[base + STRIDE]     = r1;
    out4[base + 2 * STRIDE] = r2;
    if (has3) out4[base + 3 * STRIDE] = r3;
}

extern "C" void kernel_launch(void* const* d_in, const int* in_sizes, int n_in,
                              void* d_out, int out_size)
{
    static bool attr_done = false;
    if (!attr_done) {   // idempotent attribute set (not a stream op)
        cudaFuncSetAttribute(fraud_kernel,
                             cudaFuncAttributeMaxDynamicSharedMemorySize,
                             TPAD * sizeof(float));
        attr_done = true;
    }

    // node 1: build the 97x97 G2 table (accurate math; 9409 points)
    build_table<<<(TN * TN + 255) / 256, 256>>>(
        (const float4*)d_in[1],            // fraud_W
        (const float4*)d_in[2],            // fraud_b
        (const float4*)d_in[15],           // conv_k
        (const float4*)d_in[16],           // s_W1
        (const float4*)d_in[17],           // s_b1
        (const float4*)d_in[18],           // s_W2
        (const float2*)d_in[19]);          // s_b2

    // node 2: main kernel — 296 blocks (2/SM), 512 threads, <=4 float4/thread
    const int n4 = in_sizes[0] / 4;        // 524288 float4 (2 samples each)
    fraud_kernel<<<GRID, BLOCK, TPAD * sizeof(float)>>>(
        (const float4*)d_in[0],            // x
        (const float4*)d_in[1],            // fraud_W (row 0 used)
        (const float4*)d_in[2],            // fraud_b (first 2 floats used)
        (float4*)d_out,
        n4);
}

// round 16
// speedup vs baseline: 1.0208x; 1.0208x over previous
#include <cuda_runtime.h>
#include <math.h>

// FraudDetectionHybrid — autoencoder branch is dead code (recon unused).
// R16: table path was right but occupancy-starved twice (R13: MLP=1 bug;
// R15: 37.6KB table -> only 29 warps/SM vs a ~100-cyc/sample latency chain).
// Shrink table to TN=65 (16.9KB) -> 8 blocks/SM, 64 warps = 100% occupancy,
// single wave (grid 1024, 2 float4/thread). Per sample: 2 MUFU + 4 LDS +
// ~16 FMA. rel_err bound calibrated from R13/R15 measurement: 1.64e-4 at
// delta=1/48 scaled by (48/32)^2 = 3.7e-4 worst case.

#define TN    65
#define TCNT  4225                      // 65*65
#define TPAD  4228                      // padded to /4
#define BLOCK 256

__device__ float g_tab2[TPAD];

__device__ __forceinline__ float tanh_fast(float x) {
    float y;
    asm("tanh.approx.f32 %0, %1;" : "=f"(y) : "f"(x));
    return y;
}

// ---------------- kernel 1: build G2 table (accurate math, tiny) ----------------
__global__ __launch_bounds__(256)
void build_table(const float4* __restrict__ fraud_W,   // [4,2,2] = 4 float4
                 const float4* __restrict__ fraud_b,   // [4,2]   = 2 float4
                 const float4* __restrict__ conv_k,
                 const float4* __restrict__ s_W1,
                 const float4* __restrict__ s_b1,
                 const float4* __restrict__ s_W2,
                 const float2* __restrict__ s_b2)
{
    const int idx = blockIdx.x * blockDim.x + threadIdx.x;
    if (idx >= TCNT) return;
    const int ix = idx % TN;            // h0 axis
    const int iy = idx / TN;            // h1 axis
    float h0 = (float)ix * (1.0f / 32.0f) - 1.0f;
    float h1 = (float)iy * (1.0f / 32.0f) - 1.0f;

    const float4 w1  = __ldg(fraud_W + 1);
    const float4 w2  = __ldg(fraud_W + 2);
    const float4 w3  = __ldg(fraud_W + 3);
    const float4 fb0 = __ldg(fraud_b + 0);
    const float4 fb1 = __ldg(fraud_b + 1);
    const float4 ck  = __ldg(conv_k);
    const float4 W1a = __ldg(s_W1 + 0);
    const float4 W1b = __ldg(s_W1 + 1);
    const float4 b1  = __ldg(s_b1);
    const float4 W2a = __ldg(s_W2 + 0);
    const float4 W2b = __ldg(s_W2 + 1);
    const float2 b2  = __ldg(s_b2);

    // fraud layers 2..4 (ACCURATE tanh — table absorbs no approx error here)
    float z0 = fmaf(w1.x, h0, fmaf(w1.y, h1, fb0.z));
    float z1 = fmaf(w1.z, h0, fmaf(w1.w, h1, fb0.w));
    h0 = tanhf(z0); h1 = tanhf(z1);
    z0 = fmaf(w2.x, h0, fmaf(w2.y, h1, fb1.x));
    z1 = fmaf(w2.z, h0, fmaf(w2.w, h1, fb1.y));
    h0 = tanhf(z0); h1 = tanhf(z1);
    z0 = fmaf(w3.x, h0, fmaf(w3.y, h1, fb1.z));
    z1 = fmaf(w3.z, h0, fmaf(w3.w, h1, fb1.w));
    h0 = tanhf(z0); h1 = tanhf(z1);
    // collapsed conv + sigmoid
    float zc   = fmaf(ck.x + ck.z, h0, (ck.y + ck.w) * h1);
    float conv = 1.0f / (1.0f + expf(-zc));
    // sampler 2->4 tanh
    float t0 = tanhf(fmaf(W1a.x, h0, fmaf(W1a.y, conv, b1.x)));
    float t1 = tanhf(fmaf(W1a.z, h0, fmaf(W1a.w, conv, b1.y)));
    float t2 = tanhf(fmaf(W1b.x, h0, fmaf(W1b.y, conv, b1.z)));
    float t3 = tanhf(fmaf(W1b.z, h0, fmaf(W1b.w, conv, b1.w)));
    // dl = l1 - l0 ; p0 = 1/(1+exp(dl))
    float dl = fmaf(t3, W2b.w - W2a.w, fmaf(t2, W2b.z - W2a.z,
               fmaf(t1, W2b.y - W2a.y, fmaf(t0, W2b.x - W2a.x, b2.y - b2.x))));
    g_tab2[idx] = 1.0f / (1.0f + expf(dl));
}

// ---------------- kernel 2: layer-1 tanh + smem bilinear ----------------
__global__ __launch_bounds__(BLOCK, 8)
void fraud_kernel(const float4* __restrict__ x4,
                  const float4* __restrict__ fraud_W,   // row 0 only
                  const float4* __restrict__ fraud_b,   // first 2 floats only
                  float4* __restrict__ out4)
{
    __shared__ float tab[TPAD];         // 16.9 KB -> 8 blocks/SM, occ 100%

    // grid 1024 x block 256; each thread owns 2 float4 (4 samples),
    // strided by 256 within a 512-float4 block tile -> fully coalesced.
    const int base = blockIdx.x * 512 + threadIdx.x;

    // ---- input loads in flight FIRST (MLP=2) ----
    const float4 in0 = x4[base];
    const float4 in1 = x4[base + 256];

    // ---- cooperative table stage: 1057 float4 over 256 threads ----
    {
        const float4* src = reinterpret_cast<const float4*>(g_tab2);
        float4* dst = reinterpret_cast<float4*>(tab);
#pragma unroll
        for (int k = 0; k < 5; k++) {
            int i = threadIdx.x + k * BLOCK;
            if (i < TPAD / 4) dst[i] = src[i];
        }
    }

    const float4 w0  = __ldg(fraud_W);        // layer-1 weights
    const float4 fb0 = __ldg(fraud_b);        // .x,.y = layer-1 biases
    __syncthreads();

    auto process = [&](float x0, float x1, float& p0, float& p1) {
        // fraud layer 1 (only MUFU work left)
        float h0 = tanh_fast(fmaf(w0.x, x0, fmaf(w0.y, x1, fb0.x)));
        float h1 = tanh_fast(fmaf(w0.z, x0, fmaf(w0.w, x1, fb0.y)));
        // bilinear lookup of G2(h0,h1); u,v in [0,64]
        float u = fmaf(h0, 32.0f, 32.0f);
        float v = fmaf(h1, 32.0f, 32.0f);
        int ix = min(__float2int_rd(u), TN - 2);
        int iy = min(__float2int_rd(v), TN - 2);
        float fx = u - (float)ix;
        float fy = v - (float)iy;
        const float* r = tab + iy * TN + ix;
        float v00 = r[0];
        float v01 = r[1];
        float v10 = r[TN];
        float v11 = r[TN + 1];
        float g0 = fmaf(fx, v01 - v00, v00);
        float g1 = fmaf(fx, v11 - v10, v10);
        p0 = fmaf(fy, g1 - g0, g0);
        p1 = 1.0f - p0;
    };

    float4 r0, r1;
    process(in0.x, in0.y, r0.x, r0.y);
    process(in0.z, in0.w, r0.z, r0.w);
    process(in1.x, in1.y, r1.x, r1.y);
    process(in1.z, in1.w, r1.z, r1.w);

    out4[base]       = r0;
    out4[base + 256] = r1;
}

extern "C" void kernel_launch(void* const* d_in, const int* in_sizes, int n_in,
                              void* d_out, int out_size)
{
    // node 1: build the 65x65 G2 table (accurate math; 4225 points)
    build_table<<<(TCNT + 255) / 256, 256>>>(
        (const float4*)d_in[1],            // fraud_W
        (const float4*)d_in[2],            // fraud_b
        (const float4*)d_in[15],           // conv_k
        (const float4*)d_in[16],           // s_W1
        (const float4*)d_in[17],           // s_b1
        (const float4*)d_in[18],           // s_W2
        (const float2*)d_in[19]);          // s_b2

    // node 2: main — grid 1024, block 256, 8 blocks/SM, single wave
    const int grid = in_sizes[0] / 4 / 512;   // 524288 float4 / 512 = 1024
    fraud_kernel<<<grid, BLOCK>>>(
        (const float4*)d_in[0],            // x
        (const float4*)d_in[1],            // fraud_W (row 0 used)
        (const float4*)d_in[2],            // fraud_b (first 2 floats used)
        (float4*)d_out);
}